// round 1
// baseline (speedup 1.0000x reference)
#include <cuda_runtime.h>
#include <cuda_bf16.h>
#include <cstdint>
#include <cstdio>

// ---------------- problem constants (fixed by setup_inputs) ----------------
#define S_TOT 2048
#define BATCH 16
#define FEAT  100
#define EMB   512
#define HID   512
#define NOUT  10
#define DEC   1024
#define FF    2048
#define NHEAD 8
#define DHEAD 64
#define SEP   1024
#define TROWS (SEP*BATCH)      // 16384 train rows
#define EROWS ((S_TOT-SEP)*BATCH) // 16384 eval rows (flattened e*B+b)

// ---------------- scratch (device globals; reused across stages) -----------
__device__ float g_bufA[TROWS * EMB];   // train_x  -> later h_eval
__device__ float g_bufB[TROWS * EMB];   // q        -> wo-out -> ffn2-out
__device__ float g_bufC[TROWS * EMB];   // k        -> z
__device__ float g_bufD[TROWS * EMB];   // v        -> out
__device__ float g_bufE[TROWS * EMB];   // attn out (pre-Wo)
__device__ float g_ff  [TROWS * FF];    // ffn hidden
__device__ float g_pool[BATCH * EMB];
__device__ float g_dh  [BATCH * DEC];
__device__ float g_w1  [BATCH * FEAT * HID];
__device__ float g_b1v [BATCH * HID];
__device__ float g_w2  [BATCH * HID * NOUT];
__device__ float g_b2v [BATCH * NOUT];

// ---------------- generic SGEMM 128x128x8, 256 threads, 8x8/thread --------
// A: [M,K] with row stride lda (+ z*aZ), B: [K,N] row-major (+ z*bZ),
// C: row*ldc + col (+ z*cZ).
// EPI: 0 none, 1 +bias, 2 +bias,relu, 3 encoder (+bias + y[row]*yW + yb)
#define BM 128
#define BN 128
#define BKK 8

__device__ __forceinline__ float nanclean(float v) {
    if (v != v) return 0.0f;
    return fminf(fmaxf(v, -3.402823466e38f), 3.402823466e38f);
}

template<int EPI, bool NANC>
__global__ __launch_bounds__(256)
void sgemm_kernel(const float* __restrict__ A, const float* __restrict__ Bm,
                  float* __restrict__ C,
                  int M, int N, int K, int lda, int ldc,
                  const float* __restrict__ bias, int biasZ,
                  const float* __restrict__ yv, const float* __restrict__ yW,
                  const float* __restrict__ yb,
                  long aZ, long bZ, long cZ)
{
    __shared__ float As[BKK][BM];
    __shared__ float Bs[BKK][BN];

    const float* Ab = A + (long)blockIdx.z * aZ;
    const float* Bb = Bm + (long)blockIdx.z * bZ;
    float*       Cb = C + (long)blockIdx.z * cZ;
    const float* biasb = bias ? (bias + (long)blockIdx.z * biasZ) : nullptr;

    const int m0 = blockIdx.y * BM;
    const int n0 = blockIdx.x * BN;
    const int tid = threadIdx.x;
    const int tx = tid & 15;        // 0..15 -> col group
    const int ty = tid >> 4;        // 0..15 -> row group

    const int am = tid >> 1;        // A load: row 0..127
    const int ak = (tid & 1) * 4;   // A load: k 0 or 4
    const int bk = tid >> 5;        // B load: k 0..7
    const int bn = (tid & 31) * 4;  // B load: n

    float acc[8][8];
    #pragma unroll
    for (int i = 0; i < 8; i++)
        #pragma unroll
        for (int j = 0; j < 8; j++) acc[i][j] = 0.0f;

    for (int k0 = 0; k0 < K; k0 += BKK) {
        // ---- load A tile (transposed into As[k][m]) ----
        float4 av;
        if (k0 + BKK <= K) {
            av = *(const float4*)(Ab + (size_t)(m0 + am) * lda + k0 + ak);
        } else {
            const float* ap = Ab + (size_t)(m0 + am) * lda;
            av.x = (k0 + ak + 0 < K) ? ap[k0 + ak + 0] : 0.0f;
            av.y = (k0 + ak + 1 < K) ? ap[k0 + ak + 1] : 0.0f;
            av.z = (k0 + ak + 2 < K) ? ap[k0 + ak + 2] : 0.0f;
            av.w = (k0 + ak + 3 < K) ? ap[k0 + ak + 3] : 0.0f;
        }
        if (NANC) { av.x = nanclean(av.x); av.y = nanclean(av.y);
                    av.z = nanclean(av.z); av.w = nanclean(av.w); }
        As[ak + 0][am] = av.x; As[ak + 1][am] = av.y;
        As[ak + 2][am] = av.z; As[ak + 3][am] = av.w;

        // ---- load B tile ----
        float4 bv2;
        if (k0 + bk < K) {
            bv2 = *(const float4*)(Bb + (size_t)(k0 + bk) * N + n0 + bn);
        } else {
            bv2.x = bv2.y = bv2.z = bv2.w = 0.0f;
        }
        Bs[bk][bn + 0] = bv2.x; Bs[bk][bn + 1] = bv2.y;
        Bs[bk][bn + 2] = bv2.z; Bs[bk][bn + 3] = bv2.w;

        __syncthreads();

        #pragma unroll
        for (int kk = 0; kk < BKK; kk++) {
            float ra[8], rb[8];
            #pragma unroll
            for (int i = 0; i < 8; i++) ra[i] = As[kk][ty * 8 + i];
            #pragma unroll
            for (int j = 0; j < 8; j++) rb[j] = Bs[kk][tx * 8 + j];
            #pragma unroll
            for (int i = 0; i < 8; i++)
                #pragma unroll
                for (int j = 0; j < 8; j++)
                    acc[i][j] += ra[i] * rb[j];
        }
        __syncthreads();
    }

    // ---- epilogue ----
    #pragma unroll
    for (int i = 0; i < 8; i++) {
        const int row = m0 + ty * 8 + i;
        float yval = 0.0f;
        if (EPI == 3) yval = yv[row];
        #pragma unroll
        for (int j = 0; j < 8; j++) {
            const int col = n0 + tx * 8 + j;
            float v = acc[i][j];
            if (EPI == 1) v += biasb[col];
            if (EPI == 2) { v += biasb[col]; v = fmaxf(v, 0.0f); }
            if (EPI == 3) { v += biasb[col] + yval * yW[col] + yb[col]; }
            Cb[(size_t)row * ldc + col] = v;
        }
    }
}

// ---------------- flash attention: per-thread one q row --------------------
// layouts: Q/K/V/O as [T*B, E] with head h at column h*64.
#define STILE 16
__global__ __launch_bounds__(128)
void flash_attn_kernel(const float* __restrict__ Q, const float* __restrict__ K,
                       const float* __restrict__ V, float* __restrict__ O)
{
    __shared__ float Ks[STILE][68];
    __shared__ float Vs[STILE][68];

    const int b = blockIdx.z;
    const int h = blockIdx.y;
    const int t = blockIdx.x * 128 + threadIdx.x;
    const size_t qoff = ((size_t)t * BATCH + b) * EMB + h * DHEAD;

    float q[64], o[64];
    #pragma unroll
    for (int d = 0; d < 64; d += 4) {
        float4 qv = *(const float4*)(Q + qoff + d);
        q[d] = qv.x * 0.125f; q[d+1] = qv.y * 0.125f;
        q[d+2] = qv.z * 0.125f; q[d+3] = qv.w * 0.125f;
        o[d] = 0.f; o[d+1] = 0.f; o[d+2] = 0.f; o[d+3] = 0.f;
    }
    float m = -1e30f, l = 0.0f;

    for (int s0 = 0; s0 < SEP; s0 += STILE) {
        __syncthreads();
        // 16 rows x 64 floats x 2 arrays -> 2 float4 per thread per array
        #pragma unroll
        for (int i = 0; i < 2; i++) {
            int idx = threadIdx.x + i * 128;           // 0..255 float4 units
            int r = idx >> 4;
            int d4 = (idx & 15) << 2;
            size_t off = ((size_t)(s0 + r) * BATCH + b) * EMB + h * DHEAD + d4;
            float4 kv = *(const float4*)(K + off);
            Ks[r][d4] = kv.x; Ks[r][d4+1] = kv.y; Ks[r][d4+2] = kv.z; Ks[r][d4+3] = kv.w;
            float4 vv = *(const float4*)(V + off);
            Vs[r][d4] = vv.x; Vs[r][d4+1] = vv.y; Vs[r][d4+2] = vv.z; Vs[r][d4+3] = vv.w;
        }
        __syncthreads();

        float sc[STILE];
        float tmax = -1e30f;
        #pragma unroll
        for (int s = 0; s < STILE; s++) {
            float accd = 0.0f;
            #pragma unroll
            for (int d = 0; d < 64; d++) accd += q[d] * Ks[s][d];
            sc[s] = accd;
            tmax = fmaxf(tmax, accd);
        }
        const float mnew = fmaxf(m, tmax);
        const float corr = __expf(m - mnew);
        l *= corr;
        #pragma unroll
        for (int d = 0; d < 64; d++) o[d] *= corr;
        #pragma unroll
        for (int s = 0; s < STILE; s++) {
            const float p = __expf(sc[s] - mnew);
            l += p;
            #pragma unroll
            for (int d = 0; d < 64; d++) o[d] += p * Vs[s][d];
        }
        m = mnew;
    }

    const float inv = 1.0f / l;
    #pragma unroll
    for (int d = 0; d < 64; d++) O[qoff + d] = o[d] * inv;
}

// ---------------- fused residual add + LayerNorm (E=512) -------------------
__global__ __launch_bounds__(256)
void ln_add_kernel(const float* __restrict__ A, const float* __restrict__ B,
                   const float* __restrict__ g, const float* __restrict__ be,
                   float* __restrict__ out)
{
    __shared__ float red[16];
    const int row = blockIdx.x, tid = threadIdx.x;
    const size_t base = (size_t)row * EMB;
    float x0 = A[base + tid] + B[base + tid];
    float x1 = A[base + tid + 256] + B[base + tid + 256];

    float s = x0 + x1;
    #pragma unroll
    for (int off = 16; off > 0; off >>= 1) s += __shfl_down_sync(0xffffffffu, s, off);
    if ((tid & 31) == 0) red[tid >> 5] = s;
    __syncthreads();
    if (tid < 32) {
        float v = (tid < 8) ? red[tid] : 0.0f;
        #pragma unroll
        for (int off = 4; off > 0; off >>= 1) v += __shfl_down_sync(0xffffffffu, v, off);
        if (tid == 0) red[8] = v;
    }
    __syncthreads();
    const float mean = red[8] * (1.0f / 512.0f);
    const float d0 = x0 - mean, d1 = x1 - mean;

    float sq = d0 * d0 + d1 * d1;
    #pragma unroll
    for (int off = 16; off > 0; off >>= 1) sq += __shfl_down_sync(0xffffffffu, sq, off);
    if ((tid & 31) == 0) red[tid >> 5] = sq;
    __syncthreads();
    if (tid < 32) {
        float v = (tid < 8) ? red[tid] : 0.0f;
        #pragma unroll
        for (int off = 4; off > 0; off >>= 1) v += __shfl_down_sync(0xffffffffu, v, off);
        if (tid == 0) red[9] = v;
    }
    __syncthreads();
    const float var = red[9] * (1.0f / 512.0f);
    const float r = rsqrtf(var + 1e-5f);
    out[base + tid]       = d0 * r * g[tid]       + be[tid];
    out[base + tid + 256] = d1 * r * g[tid + 256] + be[tid + 256];
}

// ---------------- mean pool over train tokens ------------------------------
__global__ void pool_kernel(const float* __restrict__ X, float* __restrict__ P)
{
    const int b = blockIdx.x;
    const int e = threadIdx.x;  // 512 threads
    float s = 0.0f;
    for (int t = 0; t < SEP; t++)
        s += X[((size_t)t * BATCH + b) * EMB + e];
    P[b * EMB + e] = s * (1.0f / (float)SEP);
}

// ---------------- small-M (16) GEMM: C[16,N] = A[16,K] @ B[K,N] ------------
// EPI: 0 none, 2 +bias,relu
template<int EPI>
__global__ __launch_bounds__(128)
void gemm16_kernel(const float* __restrict__ A, const float* __restrict__ B,
                   const float* __restrict__ bias, float* __restrict__ C,
                   int N, int K)
{
    __shared__ float As[16][256];
    const int n = blockIdx.x * 128 + threadIdx.x;
    float acc[16];
    #pragma unroll
    for (int mm = 0; mm < 16; mm++) acc[mm] = 0.0f;

    for (int k0 = 0; k0 < K; k0 += 256) {
        for (int idx = threadIdx.x; idx < 16 * 256; idx += 128) {
            const int mm = idx >> 8, kk = idx & 255;
            As[mm][kk] = A[(size_t)mm * K + k0 + kk];
        }
        __syncthreads();
        if (n < N) {
            for (int kk = 0; kk < 256; kk += 4) {
                float bv0 = B[(size_t)(k0 + kk + 0) * N + n];
                float bv1 = B[(size_t)(k0 + kk + 1) * N + n];
                float bv2 = B[(size_t)(k0 + kk + 2) * N + n];
                float bv3 = B[(size_t)(k0 + kk + 3) * N + n];
                #pragma unroll
                for (int mm = 0; mm < 16; mm++) {
                    float4 a4 = *(const float4*)&As[mm][kk];
                    acc[mm] += a4.x * bv0 + a4.y * bv1 + a4.z * bv2 + a4.w * bv3;
                }
            }
        }
        __syncthreads();
    }
    if (n < N) {
        #pragma unroll
        for (int mm = 0; mm < 16; mm++) {
            float v = acc[mm];
            if (EPI == 2) { v += bias[n]; v = fmaxf(v, 0.0f); }
            C[(size_t)mm * N + n] = v;
        }
    }
}

// ---------------- eval second matmul: out = H @ w2[b] + b2[b] --------------
// H: [e*B+b, 512], w2: [B][512][10], out: [e*B+b][10]
__global__ __launch_bounds__(320)
void eval2_kernel(const float* __restrict__ H, const float* __restrict__ W2,
                  const float* __restrict__ B2, float* __restrict__ out)
{
    __shared__ float hs[32][132];
    __shared__ float w2s[128][10];
    const int b  = blockIdx.y;
    const int e0 = blockIdx.x * 32;
    const int tid = threadIdx.x;
    const int i = tid / 10;   // e row within tile (0..31)
    const int o = tid % 10;
    float acc = 0.0f;

    for (int k0 = 0; k0 < HID; k0 += 128) {
        for (int idx = tid; idx < 32 * 128; idx += 320) {
            const int r = idx >> 7, kk = idx & 127;
            hs[r][kk] = H[((size_t)(e0 + r) * BATCH + b) * HID + k0 + kk];
        }
        for (int idx = tid; idx < 128 * 10; idx += 320) {
            w2s[idx / 10][idx % 10] =
                W2[(size_t)b * (HID * NOUT) + (size_t)(k0 + idx / 10) * NOUT + idx % 10];
        }
        __syncthreads();
        #pragma unroll 8
        for (int kk = 0; kk < 128; kk++)
            acc += hs[i][kk] * w2s[kk][o];
        __syncthreads();
    }
    out[((size_t)(e0 + i) * BATCH + b) * NOUT + o] = acc + B2[b * NOUT + o];
}

// ---------------- host launcher --------------------------------------------
static float* sym(const void* symbol) {
    void* p = nullptr;
    cudaGetSymbolAddress(&p, symbol);
    return (float*)p;
}

extern "C" void kernel_launch(void* const* d_in, const int* in_sizes, int n_in,
                              void* d_out, int out_size)
{
    const float* x       = (const float*)d_in[0];
    const float* y       = (const float*)d_in[1];
    const float* enc_W   = (const float*)d_in[2];
    const float* enc_b   = (const float*)d_in[3];
    const float* yenc_W  = (const float*)d_in[4];
    const float* yenc_b  = (const float*)d_in[5];
    const float* Wq      = (const float*)d_in[6];
    const float* Wk      = (const float*)d_in[7];
    const float* Wv      = (const float*)d_in[8];
    const float* Wo      = (const float*)d_in[9];
    const float* ln1_g   = (const float*)d_in[10];
    const float* ln1_b   = (const float*)d_in[11];
    const float* ln2_g   = (const float*)d_in[12];
    const float* ln2_b   = (const float*)d_in[13];
    const float* ffn_W1  = (const float*)d_in[14];
    const float* ffn_b1  = (const float*)d_in[15];
    const float* ffn_W2  = (const float*)d_in[16];
    const float* ffn_b2  = (const float*)d_in[17];
    const float* dec_W   = (const float*)d_in[18];
    const float* dec_b   = (const float*)d_in[19];
    const float* hw1     = (const float*)d_in[20];
    const float* hb1     = (const float*)d_in[21];
    const float* hw2     = (const float*)d_in[22];
    const float* hb2     = (const float*)d_in[23];
    // d_in[24] = single_eval_pos (fixed at 1024 by the dataset)

    float* bufA = sym(g_bufA);
    float* bufB = sym(g_bufB);
    float* bufC = sym(g_bufC);
    float* bufD = sym(g_bufD);
    float* bufE = sym(g_bufE);
    float* ff   = sym(g_ff);
    float* pool = sym(g_pool);
    float* dh   = sym(g_dh);
    float* w1   = sym(g_w1);
    float* b1v  = sym(g_b1v);
    float* w2   = sym(g_w2);
    float* b2v  = sym(g_b2v);
    float* out  = (float*)d_out;

    // 1) encoder: train_x = x[:sep] @ enc_W + enc_b + y*yenc_W + yenc_b
    sgemm_kernel<3, false><<<dim3(EMB/128, TROWS/128, 1), 256>>>(
        x, enc_W, bufA, TROWS, EMB, FEAT, FEAT, EMB,
        enc_b, 0, y, yenc_W, yenc_b, 0, 0, 0);

    // 2) q, k, v
    sgemm_kernel<0, false><<<dim3(EMB/128, TROWS/128, 1), 256>>>(
        bufA, Wq, bufB, TROWS, EMB, EMB, EMB, EMB,
        nullptr, 0, nullptr, nullptr, nullptr, 0, 0, 0);
    sgemm_kernel<0, false><<<dim3(EMB/128, TROWS/128, 1), 256>>>(
        bufA, Wk, bufC, TROWS, EMB, EMB, EMB, EMB,
        nullptr, 0, nullptr, nullptr, nullptr, 0, 0, 0);
    sgemm_kernel<0, false><<<dim3(EMB/128, TROWS/128, 1), 256>>>(
        bufA, Wv, bufD, TROWS, EMB, EMB, EMB, EMB,
        nullptr, 0, nullptr, nullptr, nullptr, 0, 0, 0);

    // 3) flash attention -> bufE
    flash_attn_kernel<<<dim3(SEP/128, NHEAD, BATCH), 128>>>(bufB, bufC, bufD, bufE);

    // 4) output projection (no bias) -> bufB
    sgemm_kernel<0, false><<<dim3(EMB/128, TROWS/128, 1), 256>>>(
        bufE, Wo, bufB, TROWS, EMB, EMB, EMB, EMB,
        nullptr, 0, nullptr, nullptr, nullptr, 0, 0, 0);

    // 5) z = LN(train_x + ao) -> bufC
    ln_add_kernel<<<TROWS, 256>>>(bufB, bufA, ln1_g, ln1_b, bufC);

    // 6) ffn hidden = relu(z @ W1 + b1)
    sgemm_kernel<2, false><<<dim3(FF/128, TROWS/128, 1), 256>>>(
        bufC, ffn_W1, ff, TROWS, FF, EMB, EMB, FF,
        ffn_b1, 0, nullptr, nullptr, nullptr, 0, 0, 0);

    // 7) ffn out = hidden @ W2 + b2 -> bufB
    sgemm_kernel<1, false><<<dim3(EMB/128, TROWS/128, 1), 256>>>(
        ff, ffn_W2, bufB, TROWS, EMB, FF, FF, EMB,
        ffn_b2, 0, nullptr, nullptr, nullptr, 0, 0, 0);

    // 8) out = LN(z + ffn) -> bufD
    ln_add_kernel<<<TROWS, 256>>>(bufB, bufC, ln2_g, ln2_b, bufD);

    // 9) pooled mean over train tokens
    pool_kernel<<<BATCH, EMB>>>(bufD, pool);

    // 10) dh = relu(pooled @ dec_W + dec_b)
    gemm16_kernel<2><<<DEC/128, 128>>>(pool, dec_W, dec_b, dh, DEC, EMB);

    // 11) hypernetwork heads (no bias)
    gemm16_kernel<0><<<(FEAT*HID)/128, 128>>>(dh, hw1, nullptr, w1, FEAT*HID, DEC);
    gemm16_kernel<0><<<HID/128, 128>>>(dh, hb1, nullptr, b1v, HID, DEC);
    gemm16_kernel<0><<<(HID*NOUT)/128, 128>>>(dh, hw2, nullptr, w2, HID*NOUT, DEC);
    gemm16_kernel<0><<<1, 128>>>(dh, hb2, nullptr, b2v, NOUT, DEC);

    // 12) eval layer 1: h = relu(nan_to_num(x_eval) @ w1[b] + b1[b]) -> bufA
    //     A rows strided by B*F, per-batch offset b*F; C rows strided by B*HID
    sgemm_kernel<2, true><<<dim3(HID/128, (S_TOT-SEP)/128, BATCH), 256>>>(
        x + (size_t)SEP * BATCH * FEAT, w1, bufA,
        S_TOT-SEP, HID, FEAT, BATCH*FEAT, BATCH*HID,
        b1v, HID, nullptr, nullptr, nullptr,
        (long)FEAT, (long)FEAT*HID, (long)HID);

    // 13) eval layer 2: out = h @ w2[b] + b2[b]
    eval2_kernel<<<dim3((S_TOT-SEP)/32, BATCH), 320>>>(bufA, w2, b2v, out);
}